// round 6
// baseline (speedup 1.0000x reference)
#include <cuda_runtime.h>
#include <cstdint>

// ============================================================
// Shaw relative positional embedding:
//   out[b,h,n,r] = (1/8) * sum_d q[b,h,n,d] * E[n-r+2048, d]
// (clip is a no-op: |n-r| <= 2047)
//
// Per 128x128 output tile, banded GEMM with portable mma.sync
// (tcgen05 is an sm_103a-only feature; this build targets sm_103):
//   warp w owns rows nl in [16w, 16w+16)
//   band cols c needed by those rows: [16w, 16w+143) -> 18 n8-blocks
//   P[nl, c] = sum_d Q[nl,d] * E[j0+c, d]     (m16n8k8 tf32, K=64)
//   out[nl, rl] = 0.125 * P[nl, nl+127-rl]    (bijection, every elem
//                                              written exactly once)
// ============================================================

#define SEQ      2048
#define DHEAD    64
#define BH       32
#define TN       128
#define TR       128
#define BAND     256          // band rows staged (255 used)
#define BROW     68           // padded SMEM row stride in floats (bank-conflict-free)
#define THREADS  256
#define NI_PER_W 18           // n8 blocks per warp (band coverage)

#define SMEM_BYTES (BAND * BROW * 4)   // 69632 B

__device__ __forceinline__ uint32_t f2tf32(float f) {
    uint32_t r;
    asm("cvt.rna.tf32.f32 %0, %1;" : "=r"(r) : "f"(f));
    return r;
}

__device__ __forceinline__ void mma_16x8x8_tf32(float c[4],
                                                const uint32_t a[4],
                                                uint32_t b0, uint32_t b1) {
    asm volatile(
        "mma.sync.aligned.m16n8k8.row.col.f32.tf32.tf32.f32 "
        "{%0,%1,%2,%3}, {%4,%5,%6,%7}, {%8,%9}, {%0,%1,%2,%3};"
        : "+f"(c[0]), "+f"(c[1]), "+f"(c[2]), "+f"(c[3])
        : "r"(a[0]), "r"(a[1]), "r"(a[2]), "r"(a[3]), "r"(b0), "r"(b1));
}

__global__ void __launch_bounds__(THREADS, 2)
shaw_relpos_kernel(const float* __restrict__ q,
                   const float* __restrict__ emb,
                   float* __restrict__ out)
{
    extern __shared__ uint32_t Bs[];   // [BAND][BROW] tf32 bits, padded rows

    const int tid  = threadIdx.x;
    const int w    = tid >> 5;         // warp id = mi block (16 rows each)
    const int lane = tid & 31;
    const int gid  = lane >> 2;        // 0..7
    const int t    = lane & 3;         // 0..3

    const int n0 = blockIdx.y * TN;
    const int r0 = blockIdx.x * TR;
    const int bz = blockIdx.z;                       // b*16 + h
    const int j0 = n0 - r0 + 2048 - (TR - 1);        // band start row in E, [1, 3841]

    // ---- Cooperative fill of E band into padded SMEM (tf32-converted) ----
    {
        const float4* e4 = (const float4*)(emb + (size_t)j0 * DHEAD);
        #pragma unroll 4
        for (int idx = tid; idx < BAND * (DHEAD / 4); idx += THREADS) {
            const int row = idx >> 4, c = idx & 15;
            float4 v = e4[row * 16 + c];
            uint4 tv = make_uint4(f2tf32(v.x), f2tf32(v.y), f2tf32(v.z), f2tf32(v.w));
            *(uint4*)(&Bs[row * BROW + c * 4]) = tv;
        }
    }

    // ---- Load this warp's A fragments (16 rows x K=64) into registers ----
    // m16n8k8 tf32 A layout: a0:(gid, 8k+t) a1:(gid+8, 8k+t) a2:(gid, 8k+t+4) a3:(gid+8, 8k+t+4)
    uint32_t a[8][4];
    {
        const float* qrow = q + ((size_t)bz * SEQ + n0 + w * 16) * DHEAD;
        const float* q_lo = qrow + (size_t)gid * DHEAD;
        const float* q_hi = qrow + (size_t)(gid + 8) * DHEAD;
        #pragma unroll
        for (int k = 0; k < 8; k++) {
            const int c0 = k * 8 + t;
            a[k][0] = f2tf32(q_lo[c0]);
            a[k][1] = f2tf32(q_hi[c0]);
            a[k][2] = f2tf32(q_lo[c0 + 4]);
            a[k][3] = f2tf32(q_hi[c0 + 4]);
        }
    }
    __syncthreads();

    // ---- Band-restricted MMA + immediate diagonal-extract store ----
    // Output pointer for this warp's 16-row strip
    float* outp = out + ((size_t)bz * SEQ + n0 + w * 16) * SEQ + r0;

    const int ni_lo = 2 * w;
    #pragma unroll 1
    for (int nn = 0; nn < NI_PER_W; nn++) {
        const int ni = ni_lo + nn;
        float c[4] = {0.f, 0.f, 0.f, 0.f};

        // B fragment (k8n8, col-major op): b0 = E[8ni+gid][8k+t], b1 = +4
        const uint32_t* brow = &Bs[(ni * 8 + gid) * BROW];
        #pragma unroll
        for (int k = 0; k < 8; k++) {
            uint32_t b0 = brow[k * 8 + t];
            uint32_t b1 = brow[k * 8 + t + 4];
            mma_16x8x8_tf32(c, a[k], b0, b1);
        }

        // C frag: c0:(gid, 2t) c1:(gid, 2t+1) c2:(gid+8, 2t) c3:(gid+8, 2t+1)
        // band col cc -> rl = nl + 127 - cc  (nl local to tile)
        const int cc  = ni * 8 + t * 2;
        const int nl0 = w * 16 + gid;
        const int rl0 = nl0 + 127 - cc;        // row gid,   col cc
        const int rl2 = rl0 + 8;               // row gid+8, col cc

        float* o_lo = outp + (size_t)gid * SEQ;
        float* o_hi = o_lo + (size_t)8 * SEQ;
        if ((unsigned)rl0 < TR)       o_lo[rl0]     = 0.125f * c[0];
        if ((unsigned)(rl0 - 1) < TR) o_lo[rl0 - 1] = 0.125f * c[1];
        if ((unsigned)rl2 < TR)       o_hi[rl2]     = 0.125f * c[2];
        if ((unsigned)(rl2 - 1) < TR) o_hi[rl2 - 1] = 0.125f * c[3];
    }
}

// ---------------- launch ----------------

extern "C" void kernel_launch(void* const* d_in, const int* in_sizes, int n_in,
                              void* d_out, int out_size) {
    // metadata order: q [2,16,2048,64], k (unused), rel_pos_emb [4097,64]
    const float* q   = (const float*)d_in[0];
    const float* emb = (const float*)d_in[2];
    for (int i = 0; i < n_in; i++) {
        if (in_sizes[i] == 4097 * 64) emb = (const float*)d_in[i];
    }
    float* out = (float*)d_out;

    cudaFuncSetAttribute(shaw_relpos_kernel,
                         cudaFuncAttributeMaxDynamicSharedMemorySize, SMEM_BYTES);

    dim3 grid(SEQ / TR, SEQ / TN, BH);   // 16 x 16 x 32 = 8192 CTAs
    shaw_relpos_kernel<<<grid, THREADS, SMEM_BYTES>>>(q, emb, out);
}

// round 8
// speedup vs baseline: 1.1514x; 1.1514x over previous
#include <cuda_runtime.h>
#include <cstdint>

// ============================================================
// Shaw relative positional embedding:
//   out[b,h,n,r] = (1/8) * sum_d q[b,h,n,d] * E[n-r+2048, d]
// (clip is a no-op: |n-r| <= 2047)
//
// Per 128x128 output tile, banded GEMM with mma.sync m16n8k8 tf32.
//   warp w owns rows nl in [16w, 16w+16)
//   band cols c needed: [16w, 16w+144) -> 18 n8-blocks, accumulated
//   entirely in registers (72 floats/thread), then scattered into a
//   SMEM staging tile (reusing the band region) and stored with
//   fully-coalesced float4 STG. This removes the scattered-STG L1
//   wavefront storm that bounded the previous round (L1tex 91.5%).
// ============================================================

#define SEQ      2048
#define DHEAD    64
#define BH       32
#define TN       128
#define TR       128
#define BAND     256          // band rows staged (255 used)
#define BROW     68           // padded SMEM row stride (floats), conflict-free LDS
#define OROW     132          // staging row stride (floats): (4*nl+rl)%32 ~conflict-free
#define THREADS  256
#define NI_PER_W 18           // n8 blocks per warp (band coverage)

#define SMEM_BYTES (BAND * BROW * 4)   // 69632 B  (>= 128*OROW*4 = 67584 staging)

__device__ __forceinline__ uint32_t f2tf32(float f) {
    uint32_t r;
    asm("cvt.rna.tf32.f32 %0, %1;" : "=r"(r) : "f"(f));
    return r;
}

__device__ __forceinline__ void mma_16x8x8_tf32(float c[4],
                                                const uint32_t a[4],
                                                uint32_t b0, uint32_t b1) {
    asm volatile(
        "mma.sync.aligned.m16n8k8.row.col.f32.tf32.tf32.f32 "
        "{%0,%1,%2,%3}, {%4,%5,%6,%7}, {%8,%9}, {%0,%1,%2,%3};"
        : "+f"(c[0]), "+f"(c[1]), "+f"(c[2]), "+f"(c[3])
        : "r"(a[0]), "r"(a[1]), "r"(a[2]), "r"(a[3]), "r"(b0), "r"(b1));
}

__global__ void __launch_bounds__(THREADS, 2)
shaw_relpos_kernel(const float* __restrict__ q,
                   const float* __restrict__ emb,
                   float* __restrict__ out)
{
    extern __shared__ uint32_t smem_u32[];
    uint32_t* Bs  = smem_u32;                 // [BAND][BROW] tf32 bits (compute phase)
    float* outs   = (float*)smem_u32;         // [128][OROW]  staging (epilogue phase)

    const int tid  = threadIdx.x;
    const int w    = tid >> 5;                // warp id = 16-row block
    const int lane = tid & 31;
    const int gid  = lane >> 2;               // 0..7
    const int t    = lane & 3;                // 0..3

    const int n0 = blockIdx.y * TN;
    const int r0 = blockIdx.x * TR;
    const int bz = blockIdx.z;                       // b*16 + h
    const int j0 = n0 - r0 + 2048 - (TR - 1);        // band start row in E, [1, 3841]

    // ---- Cooperative fill of E band into padded SMEM (tf32-converted) ----
    {
        const float4* e4 = (const float4*)(emb + (size_t)j0 * DHEAD);
        #pragma unroll 4
        for (int idx = tid; idx < BAND * (DHEAD / 4); idx += THREADS) {
            const int row = idx >> 4, c = idx & 15;
            float4 v = e4[row * 16 + c];
            uint4 tv = make_uint4(f2tf32(v.x), f2tf32(v.y), f2tf32(v.z), f2tf32(v.w));
            *(uint4*)(&Bs[row * BROW + c * 4]) = tv;
        }
    }

    // ---- A fragments (16 rows x K=64) -> registers (overlaps band fill) ----
    // m16n8k8 tf32 A layout: a0:(gid, 8k+t) a1:(gid+8, 8k+t) a2:(gid, 8k+t+4) a3:(gid+8, 8k+t+4)
    uint32_t a[8][4];
    {
        const float* qrow = q + ((size_t)bz * SEQ + n0 + w * 16) * DHEAD;
        const float* q_lo = qrow + (size_t)gid * DHEAD;
        const float* q_hi = qrow + (size_t)(gid + 8) * DHEAD;
        #pragma unroll
        for (int k = 0; k < 8; k++) {
            const int c0 = k * 8 + t;
            a[k][0] = f2tf32(q_lo[c0]);
            a[k][1] = f2tf32(q_hi[c0]);
            a[k][2] = f2tf32(q_lo[c0 + 4]);
            a[k][3] = f2tf32(q_hi[c0 + 4]);
        }
    }
    __syncthreads();

    // ---- Band-restricted MMA, all accumulators register-resident ----
    float acc[NI_PER_W][4];
    {
        const int ni_lo = 2 * w;
        #pragma unroll
        for (int nn = 0; nn < NI_PER_W; nn++) {
            acc[nn][0] = acc[nn][1] = acc[nn][2] = acc[nn][3] = 0.f;
            const uint32_t* brow = &Bs[((ni_lo + nn) * 8 + gid) * BROW];
            #pragma unroll
            for (int k = 0; k < 8; k++) {
                uint32_t b0 = brow[k * 8 + t];
                uint32_t b1 = brow[k * 8 + t + 4];
                mma_16x8x8_tf32(acc[nn], a[k], b0, b1);
            }
        }
    }
    __syncthreads();   // all warps done reading the band before overwrite

    // ---- Scatter accumulators into SMEM staging (diag extraction) ----
    // C frag: c0:(gid, cc) c1:(gid, cc+1) c2:(gid+8, cc) c3:(gid+8, cc+1), cc = ni*8+2t
    // rl = nl + 127 - col;  bijective onto the 128x128 tile.
    {
        const int ni_lo = 2 * w;
        const int nlo = w * 16 + gid;       // rows nlo and nlo+8
        float* s_lo = outs + (size_t)nlo * OROW;
        float* s_hi = s_lo + (size_t)8 * OROW;
        #pragma unroll
        for (int nn = 0; nn < NI_PER_W; nn++) {
            const int cc  = (ni_lo + nn) * 8 + t * 2;
            const int rl0 = nlo + 127 - cc;          // row nlo,   col cc
            const int rl2 = rl0 + 8;                 // row nlo+8, col cc
            if ((unsigned)rl0 < TR)       s_lo[rl0]     = 0.125f * acc[nn][0];
            if ((unsigned)(rl0 - 1) < TR) s_lo[rl0 - 1] = 0.125f * acc[nn][1];
            if ((unsigned)rl2 < TR)       s_hi[rl2]     = 0.125f * acc[nn][2];
            if ((unsigned)(rl2 - 1) < TR) s_hi[rl2 - 1] = 0.125f * acc[nn][3];
        }
    }
    __syncthreads();

    // ---- Coalesced float4 store of the 128x128 tile ----
    {
        const size_t obase = ((size_t)bz * SEQ + n0) * SEQ + r0;
        #pragma unroll 4
        for (int idx = tid; idx < TN * (TR / 4); idx += THREADS) {
            const int row = idx >> 5, c = idx & 31;
            float4 v = *(const float4*)(outs + (size_t)row * OROW + c * 4);
            *(float4*)(out + obase + (size_t)row * SEQ + c * 4) = v;
        }
    }
}

// ---------------- launch ----------------

extern "C" void kernel_launch(void* const* d_in, const int* in_sizes, int n_in,
                              void* d_out, int out_size) {
    // metadata order: q [2,16,2048,64], k (unused), rel_pos_emb [4097,64]
    const float* q   = (const float*)d_in[0];
    const float* emb = (const float*)d_in[2];
    for (int i = 0; i < n_in; i++) {
        if (in_sizes[i] == 4097 * 64) emb = (const float*)d_in[i];
    }
    float* out = (float*)d_out;

    cudaFuncSetAttribute(shaw_relpos_kernel,
                         cudaFuncAttributeMaxDynamicSharedMemorySize, SMEM_BYTES);

    dim3 grid(SEQ / TR, SEQ / TN, BH);   // 16 x 16 x 32 = 8192 CTAs
    shaw_relpos_kernel<<<grid, THREADS, SMEM_BYTES>>>(q, emb, out);
}

// round 10
// speedup vs baseline: 1.2791x; 1.1109x over previous
#include <cuda_runtime.h>
#include <cstdint>

// ============================================================
// Shaw relative positional embedding:
//   out[b,h,n,r] = (1/8) * sum_d q[b,h,n,d] * E[n-r+2048, d]
// (clip is a no-op: |n-r| <= 2047)
//
// Per 128x128 output tile, banded GEMM with mma.sync m16n8k8 tf32.
//   warp w owns rows nl in [16w, 16w+16)
//   band cols c needed: [16w, 16w+144) -> 18 n8-blocks, accumulated
//   in registers; diagonal-extracted via SMEM staging; coalesced
//   float4 stores.
// R9 changes vs R8:
//   * Q tile staged through SMEM (coalesced fill + conflict-free
//     LDS.32 fragment reads) -- kills the ~256 wf/warp scattered
//     LDG.32 A-fragment path that dominated L1tex (86%).
//   * 1/8 scale folded into the Q tf32 conversion (exact: 2^-3).
// ============================================================

#define SEQ      2048
#define DHEAD    64
#define BH       32
#define TN       128
#define TR       128
#define BAND     256          // band rows staged (255 used)
#define BROW     68           // band SMEM row stride (floats), conflict-free
#define QROW     68           // Q SMEM row stride (floats), conflict-free
#define OROW     132          // staging row stride (floats)
#define THREADS  256
#define NI_PER_W 18           // n8 blocks per warp (band coverage)

#define BS_BYTES   (BAND * BROW * 4)              // 69632
#define QS_BYTES   (TN * QROW * 4)                // 34816
#define SMEM_BYTES (BS_BYTES + QS_BYTES)          // 104448  (occ 2: 204KB/SM)
// epilogue staging (128*OROW*4 = 67584) aliases the Bs region only

__device__ __forceinline__ uint32_t f2tf32(float f) {
    uint32_t r;
    asm("cvt.rna.tf32.f32 %0, %1;" : "=r"(r) : "f"(f));
    return r;
}

__device__ __forceinline__ void mma_16x8x8_tf32(float c[4],
                                                const uint32_t a[4],
                                                uint32_t b0, uint32_t b1) {
    asm volatile(
        "mma.sync.aligned.m16n8k8.row.col.f32.tf32.tf32.f32 "
        "{%0,%1,%2,%3}, {%4,%5,%6,%7}, {%8,%9}, {%0,%1,%2,%3};"
        : "+f"(c[0]), "+f"(c[1]), "+f"(c[2]), "+f"(c[3])
        : "r"(a[0]), "r"(a[1]), "r"(a[2]), "r"(a[3]), "r"(b0), "r"(b1));
}

__global__ void __launch_bounds__(THREADS, 2)
shaw_relpos_kernel(const float* __restrict__ q,
                   const float* __restrict__ emb,
                   float* __restrict__ out)
{
    extern __shared__ uint32_t smem_u32[];
    uint32_t* Bs = smem_u32;                       // [BAND][BROW] (compute phase)
    uint32_t* Qs = smem_u32 + BAND * BROW;         // [TN][QROW]   (compute phase)
    float* outs  = (float*)smem_u32;               // [128][OROW]  (epilogue, aliases Bs)

    const int tid  = threadIdx.x;
    const int w    = tid >> 5;                // warp id = 16-row block
    const int lane = tid & 31;
    const int gid  = lane >> 2;               // 0..7
    const int t    = lane & 3;                // 0..3

    const int n0 = blockIdx.y * TN;
    const int r0 = blockIdx.x * TR;
    const int bz = blockIdx.z;                       // b*16 + h
    const int j0 = n0 - r0 + 2048 - (TR - 1);        // band start row in E, [1, 3841]

    // ---- Cooperative fill: E band (tf32) ----
    {
        const float4* e4 = (const float4*)(emb + (size_t)j0 * DHEAD);
        #pragma unroll 4
        for (int idx = tid; idx < BAND * (DHEAD / 4); idx += THREADS) {
            const int row = idx >> 4, c = idx & 15;
            float4 v = e4[row * 16 + c];
            uint4 tv = make_uint4(f2tf32(v.x), f2tf32(v.y), f2tf32(v.z), f2tf32(v.w));
            *(uint4*)(&Bs[row * BROW + c * 4]) = tv;
        }
    }
    // ---- Cooperative fill: Q tile (tf32, scale 1/8 folded in -- exact) ----
    {
        const float4* q4 = (const float4*)(q + ((size_t)bz * SEQ + n0) * DHEAD);
        #pragma unroll 4
        for (int idx = tid; idx < TN * (DHEAD / 4); idx += THREADS) {
            const int row = idx >> 4, c = idx & 15;
            float4 v = q4[row * 16 + c];
            uint4 tv = make_uint4(f2tf32(0.125f * v.x), f2tf32(0.125f * v.y),
                                  f2tf32(0.125f * v.z), f2tf32(0.125f * v.w));
            *(uint4*)(&Qs[row * QROW + c * 4]) = tv;
        }
    }
    __syncthreads();

    // ---- A fragments (16 rows x K=64) from SMEM, conflict-free LDS.32 ----
    // m16n8k8 tf32 A: a0:(gid, 8k+t) a1:(gid+8, 8k+t) a2:(gid, 8k+t+4) a3:(gid+8, 8k+t+4)
    uint32_t a[8][4];
    {
        const uint32_t* q_lo = &Qs[(w * 16 + gid) * QROW];
        const uint32_t* q_hi = q_lo + 8 * QROW;
        #pragma unroll
        for (int k = 0; k < 8; k++) {
            const int c0 = k * 8 + t;
            a[k][0] = q_lo[c0];
            a[k][1] = q_hi[c0];
            a[k][2] = q_lo[c0 + 4];
            a[k][3] = q_hi[c0 + 4];
        }
    }

    // ---- Band-restricted MMA, accumulators register-resident ----
    float acc[NI_PER_W][4];
    {
        const int ni_lo = 2 * w;
        #pragma unroll
        for (int nn = 0; nn < NI_PER_W; nn++) {
            acc[nn][0] = acc[nn][1] = acc[nn][2] = acc[nn][3] = 0.f;
            const uint32_t* brow = &Bs[((ni_lo + nn) * 8 + gid) * BROW];
            #pragma unroll
            for (int k = 0; k < 8; k++) {
                uint32_t b0 = brow[k * 8 + t];
                uint32_t b1 = brow[k * 8 + t + 4];
                mma_16x8x8_tf32(acc[nn], a[k], b0, b1);
            }
        }
    }
    __syncthreads();   // all warps done reading Bs before staging overwrite

    // ---- Scatter accumulators into SMEM staging (diag extraction) ----
    // C frag: c0:(gid, cc) c1:(gid, cc+1) c2:(gid+8, cc) c3:(gid+8, cc+1), cc = ni*8+2t
    // rl = nl + 127 - col; bijective onto the 128x128 tile. Scale already in Q.
    {
        const int ni_lo = 2 * w;
        const int nlo = w * 16 + gid;       // rows nlo and nlo+8
        float* s_lo = outs + (size_t)nlo * OROW;
        float* s_hi = s_lo + (size_t)8 * OROW;
        #pragma unroll
        for (int nn = 0; nn < NI_PER_W; nn++) {
            const int cc  = (ni_lo + nn) * 8 + t * 2;
            const int rl0 = nlo + 127 - cc;          // row nlo,   col cc
            const int rl2 = rl0 + 8;                 // row nlo+8, col cc
            if ((unsigned)rl0 < TR)       s_lo[rl0]     = acc[nn][0];
            if ((unsigned)(rl0 - 1) < TR) s_lo[rl0 - 1] = acc[nn][1];
            if ((unsigned)rl2 < TR)       s_hi[rl2]     = acc[nn][2];
            if ((unsigned)(rl2 - 1) < TR) s_hi[rl2 - 1] = acc[nn][3];
        }
    }
    __syncthreads();

    // ---- Coalesced float4 store of the 128x128 tile ----
    {
        const size_t obase = ((size_t)bz * SEQ + n0) * SEQ + r0;
        #pragma unroll 4
        for (int idx = tid; idx < TN * (TR / 4); idx += THREADS) {
            const int row = idx >> 5, c = idx & 31;
            float4 v = *(const float4*)(outs + (size_t)row * OROW + c * 4);
            *(float4*)(out + obase + (size_t)row * SEQ + c * 4) = v;
        }
    }
}

// ---------------- launch ----------------

extern "C" void kernel_launch(void* const* d_in, const int* in_sizes, int n_in,
                              void* d_out, int out_size) {
    // metadata order: q [2,16,2048,64], k (unused), rel_pos_emb [4097,64]
    const float* q   = (const float*)d_in[0];
    const float* emb = (const float*)d_in[2];
    for (int i = 0; i < n_in; i++) {
        if (in_sizes[i] == 4097 * 64) emb = (const float*)d_in[i];
    }
    float* out = (float*)d_out;

    cudaFuncSetAttribute(shaw_relpos_kernel,
                         cudaFuncAttributeMaxDynamicSharedMemorySize, SMEM_BYTES);

    dim3 grid(SEQ / TR, SEQ / TN, BH);   // 16 x 16 x 32 = 8192 CTAs
    shaw_relpos_kernel<<<grid, THREADS, SMEM_BYTES>>>(q, emb, out);
}

// round 11
// speedup vs baseline: 1.3417x; 1.0490x over previous
#include <cuda_runtime.h>
#include <cstdint>

// ============================================================
// Shaw relative positional embedding:
//   out[b,h,n,r] = (1/8) * sum_d q[b,h,n,d] * E[n-r+2048, d]
// (clip is a no-op: |n-r| <= 2047)
//
// Per 128x128 output tile, banded GEMM with mma.sync m16n8k8 tf32.
// R11 changes vs R10 (both move traffic off the L1 wavefront path):
//   * Q tile + E band filled by per-row cp.async.bulk (TMA) G2S with
//     mbarrier completion; raw f32 in SMEM, cvt.rna at consumption
//     (bit-identical arithmetic; 0.125 folded into the A cvt).
//   * Output tile stored by per-row cp.async.bulk S2G from staging
//     (kills the readback-LDS + STG path).
// ============================================================

#define SEQ      2048
#define DHEAD    64
#define BH       32
#define TN       128
#define TR       128
#define BAND     256          // band rows staged (255..256 used)
#define BROW     68           // band SMEM row stride (floats): 272B = 17*16, conflict-free
#define QROW     68           // Q SMEM row stride (floats)
#define OROW     132          // staging row stride (floats): 528B = 33*16
#define THREADS  256
#define NI_PER_W 18           // n8 blocks per warp (band coverage)

// SMEM: [0,16) mbarrier; [32, +Bs) band; then Qs. Staging aliases Bs.
#define SMEM_MBAR   0
#define SMEM_BS_OFF 32
#define BS_BYTES    (BAND * BROW * 4)              // 69632
#define QS_BYTES    (TN * QROW * 4)                // 34816
#define SMEM_BYTES  (SMEM_BS_OFF + BS_BYTES + QS_BYTES)   // 104480 (occ 2)
#define FILL_BYTES  (BAND * DHEAD * 4 + TN * DHEAD * 4)   // 98304

__device__ __forceinline__ uint32_t smem_u32addr(const void* p) {
    uint32_t a;
    asm("{ .reg .u64 t; cvta.to.shared.u64 t, %1; cvt.u32.u64 %0, t; }" : "=r"(a) : "l"(p));
    return a;
}

__device__ __forceinline__ uint32_t f2tf32(float f) {
    uint32_t r;
    asm("cvt.rna.tf32.f32 %0, %1;" : "=r"(r) : "f"(f));
    return r;
}

__device__ __forceinline__ void mma_16x8x8_tf32(float c[4],
                                                const uint32_t a[4],
                                                uint32_t b0, uint32_t b1) {
    asm volatile(
        "mma.sync.aligned.m16n8k8.row.col.f32.tf32.tf32.f32 "
        "{%0,%1,%2,%3}, {%4,%5,%6,%7}, {%8,%9}, {%0,%1,%2,%3};"
        : "+f"(c[0]), "+f"(c[1]), "+f"(c[2]), "+f"(c[3])
        : "r"(a[0]), "r"(a[1]), "r"(a[2]), "r"(a[3]), "r"(b0), "r"(b1));
}

__device__ __forceinline__ void bulk_g2s(uint32_t smem_dst, const void* gmem_src,
                                         uint32_t bytes, uint32_t mbar) {
    uint64_t g;
    asm("cvta.to.global.u64 %0, %1;" : "=l"(g) : "l"(gmem_src));
    asm volatile(
        "cp.async.bulk.shared::cta.global.mbarrier::complete_tx::bytes "
        "[%0], [%1], %2, [%3];"
        :: "r"(smem_dst), "l"(g), "r"(bytes), "r"(mbar) : "memory");
}

__device__ __forceinline__ void bulk_s2g(void* gmem_dst, uint32_t smem_src,
                                         uint32_t bytes) {
    uint64_t g;
    asm("cvta.to.global.u64 %0, %1;" : "=l"(g) : "l"(gmem_dst));
    asm volatile(
        "cp.async.bulk.global.shared::cta.bulk_group [%0], [%1], %2;"
        :: "l"(g), "r"(smem_src), "r"(bytes) : "memory");
}

__global__ void __launch_bounds__(THREADS, 2)
shaw_relpos_kernel(const float* __restrict__ q,
                   const float* __restrict__ emb,
                   float* __restrict__ out)
{
    extern __shared__ char smem_raw[];
    const uint32_t sb = smem_u32addr(smem_raw);
    const uint32_t mbar = sb + SMEM_MBAR;

    float* Bs   = (float*)(smem_raw + SMEM_BS_OFF);          // [BAND][BROW] raw f32
    float* Qs   = (float*)(smem_raw + SMEM_BS_OFF + BS_BYTES); // [TN][QROW] raw f32
    float* outs = (float*)(smem_raw + SMEM_BS_OFF);          // [128][OROW] staging (aliases Bs)

    const int tid  = threadIdx.x;
    const int w    = tid >> 5;                // warp id = 16-row block
    const int lane = tid & 31;
    const int gid  = lane >> 2;               // 0..7
    const int t    = lane & 3;                // 0..3

    const int n0 = blockIdx.y * TN;
    const int r0 = blockIdx.x * TR;
    const int bz = blockIdx.z;                       // b*16 + h
    const int j0 = n0 - r0 + 2048 - (TR - 1);        // band start row in E, [1, 3841]

    // ---- mbarrier init, then async fills ----
    if (tid == 0) {
        asm volatile("mbarrier.init.shared.b64 [%0], %1;" :: "r"(mbar), "r"(1) : "memory");
    }
    __syncthreads();
    if (tid == 0) {
        asm volatile("mbarrier.arrive.expect_tx.shared.b64 _, [%0], %1;"
                     :: "r"(mbar), "r"((uint32_t)FILL_BYTES) : "memory");
    }
    // E band: 256 rows x 256 B into padded rows (dst stride 272B = 17*16)
    {
        const float* src = emb + ((size_t)j0 + tid) * DHEAD;
        bulk_g2s(sb + SMEM_BS_OFF + (uint32_t)tid * (BROW * 4), src, DHEAD * 4, mbar);
    }
    // Q tile: 128 rows x 256 B
    if (tid < TN) {
        const float* src = q + ((size_t)bz * SEQ + n0 + tid) * DHEAD;
        bulk_g2s(sb + SMEM_BS_OFF + BS_BYTES + (uint32_t)tid * (QROW * 4), src, DHEAD * 4, mbar);
    }
    // wait (parity 0)
    {
        uint32_t done;
        asm volatile(
            "{\n\t.reg .pred p;\n\t"
            "mbarrier.try_wait.parity.acquire.cta.shared::cta.b64 p, [%1], 0;\n\t"
            "selp.b32 %0, 1, 0, p;\n\t}"
            : "=r"(done) : "r"(mbar) : "memory");
        if (!done) {
            asm volatile(
                "{\n\t.reg .pred P1;\n\t"
                "WAIT_LOOP_%=:\n\t"
                "mbarrier.try_wait.parity.acquire.cta.shared::cta.b64 P1, [%0], 0, 0x989680;\n\t"
                "@P1 bra.uni WAIT_DONE_%=;\n\t"
                "bra.uni WAIT_LOOP_%=;\n\t"
                "WAIT_DONE_%=:\n\t}"
                :: "r"(mbar) : "memory");
        }
    }

    // ---- A fragments (16 rows x K=64) from SMEM, cvt.rna with 1/8 fold ----
    // m16n8k8 tf32 A: a0:(gid, 8k+t) a1:(gid+8, 8k+t) a2:(gid, 8k+t+4) a3:(gid+8, 8k+t+4)
    uint32_t a[8][4];
    {
        const float* q_lo = &Qs[(w * 16 + gid) * QROW];
        const float* q_hi = q_lo + 8 * QROW;
        #pragma unroll
        for (int k = 0; k < 8; k++) {
            const int c0 = k * 8 + t;
            a[k][0] = f2tf32(0.125f * q_lo[c0]);
            a[k][1] = f2tf32(0.125f * q_hi[c0]);
            a[k][2] = f2tf32(0.125f * q_lo[c0 + 4]);
            a[k][3] = f2tf32(0.125f * q_hi[c0 + 4]);
        }
    }

    // ---- Band-restricted MMA, accumulators register-resident ----
    float acc[NI_PER_W][4];
    {
        const int ni_lo = 2 * w;
        #pragma unroll
        for (int nn = 0; nn < NI_PER_W; nn++) {
            acc[nn][0] = acc[nn][1] = acc[nn][2] = acc[nn][3] = 0.f;
            const float* brow = &Bs[((ni_lo + nn) * 8 + gid) * BROW];
            #pragma unroll
            for (int k = 0; k < 8; k++) {
                uint32_t b0 = f2tf32(brow[k * 8 + t]);
                uint32_t b1 = f2tf32(brow[k * 8 + t + 4]);
                mma_16x8x8_tf32(acc[nn], a[k], b0, b1);
            }
        }
    }
    __syncthreads();   // all warps done reading Bs before staging overwrite

    // ---- Scatter accumulators into SMEM staging (diag extraction) ----
    // C frag: c0:(gid, cc) c1:(gid, cc+1) c2:(gid+8, cc) c3:(gid+8, cc+1), cc = ni*8+2t
    // rl = nl + 127 - col; bijective onto the 128x128 tile. Scale already in A.
    {
        const int ni_lo = 2 * w;
        const int nlo = w * 16 + gid;       // rows nlo and nlo+8
        float* s_lo = outs + (size_t)nlo * OROW;
        float* s_hi = s_lo + (size_t)8 * OROW;
        #pragma unroll
        for (int nn = 0; nn < NI_PER_W; nn++) {
            const int cc  = (ni_lo + nn) * 8 + t * 2;
            const int rl0 = nlo + 127 - cc;          // row nlo,   col cc
            const int rl2 = rl0 + 8;                 // row nlo+8, col cc
            if ((unsigned)rl0 < TR)       s_lo[rl0]     = acc[nn][0];
            if ((unsigned)(rl0 - 1) < TR) s_lo[rl0 - 1] = acc[nn][1];
            if ((unsigned)rl2 < TR)       s_hi[rl2]     = acc[nn][2];
            if ((unsigned)(rl2 - 1) < TR) s_hi[rl2 - 1] = acc[nn][3];
        }
    }
    __syncthreads();
    asm volatile("fence.proxy.async.shared::cta;" ::: "memory");

    // ---- Per-row TMA bulk store: staging -> gmem (512 B rows) ----
    if (tid < TN) {
        float* dst = out + ((size_t)bz * SEQ + n0 + tid) * SEQ + r0;
        bulk_s2g(dst, sb + SMEM_BS_OFF + (uint32_t)tid * (OROW * 4), TR * 4);
    }
    asm volatile("cp.async.bulk.commit_group;" ::: "memory");
    asm volatile("cp.async.bulk.wait_group 0;" ::: "memory");
}

// ---------------- launch ----------------

extern "C" void kernel_launch(void* const* d_in, const int* in_sizes, int n_in,
                              void* d_out, int out_size) {
    // metadata order: q [2,16,2048,64], k (unused), rel_pos_emb [4097,64]
    const float* q   = (const float*)d_in[0];
    const float* emb = (const float*)d_in[2];
    for (int i = 0; i < n_in; i++) {
        if (in_sizes[i] == 4097 * 64) emb = (const float*)d_in[i];
    }
    float* out = (float*)d_out;

    cudaFuncSetAttribute(shaw_relpos_kernel,
                         cudaFuncAttributeMaxDynamicSharedMemorySize, SMEM_BYTES);

    dim3 grid(SEQ / TR, SEQ / TN, BH);   // 16 x 16 x 32 = 8192 CTAs
    shaw_relpos_kernel<<<grid, THREADS, SMEM_BYTES>>>(q, emb, out);
}